// round 1
// baseline (speedup 1.0000x reference)
#include <cuda_runtime.h>

// MultiDirectionPattern: masked 8-direction pooling + saliency gather.
//
// Inputs (metadata order):
//   d_in[0]: x        float32  (B, C, 7, 7)      B=256, C=2048
//   d_in[1]: s        float32  (B, 1, 56, 56)
//   d_in[2]: feat_mask float32 (8, 7, 7)
//   d_in[3]: sal_idx  int32    (8, N)
// Output (float32, concatenated):
//   feat     (B, C, 2, 4)   = B*C*8 elems
//   sal_feat (B, N, 2, 4)   = B*N*8 elems

static constexpr int HW      = 49;    // 7*7
static constexpr int ROWPAD  = 52;    // pad row to 52 floats (208B, 16B aligned)
static constexpr int TPB     = 128;   // threads per block
static constexpr int SROW    = 3136;  // 56*56
static constexpr int SMEM_FLOATS = TPB * ROWPAD + 8 * HW; // 6656 + 392 = 7048

// Scaled, transposed mask: g_mask_t[k*8 + p] = feat_mask[p][k] / count[p]
__device__ float g_mask_t[8 * HW];

__global__ void prep_mask_kernel(const float* __restrict__ fm) {
    __shared__ float invc[8];
    int t = threadIdx.x;
    if (t < 8) {
        int c = 0;
        #pragma unroll
        for (int k = 0; k < HW; ++k) c += (fm[t * HW + k] != 0.0f) ? 1 : 0;
        invc[t] = 1.0f / (float)c;
    }
    __syncthreads();
    for (int i = t; i < 8 * HW; i += blockDim.x) {
        int k = i >> 3;
        int p = i & 7;
        g_mask_t[i] = fm[p * HW + k] * invc[p];
    }
}

__global__ __launch_bounds__(TPB) void fused_kernel(
    const float* __restrict__ x,
    const float* __restrict__ s,
    const int*   __restrict__ sal_idx,
    float*       __restrict__ out,
    int rows,            // B*C
    int nfb,             // number of feat blocks
    int N,               // saliency points per direction
    long long feat_elems // rows*8 (offset of sal_feat in out)
) {
    __shared__ __align__(16) float sm[SMEM_FLOATS];
    const int blk = blockIdx.x;
    const int t   = threadIdx.x;

    if (blk < nfb) {
        // ------------- feat part: 128 rows of 49 floats -------------
        float* sm_x = sm;
        float* sm_m = sm + TPB * ROWPAD;

        // stage scaled transposed mask (392 floats)
        for (int i = t; i < 8 * HW; i += TPB) sm_m[i] = g_mask_t[i];

        const long long row0 = (long long)blk * TPB;
        const int rows_here = (rows - (int)row0) < TPB ? (rows - (int)row0) : TPB;
        const float* xb = x + row0 * HW;
        const int lim = rows_here * HW;

        // coalesced global -> padded smem
        for (int i = t; i < lim; i += TPB) {
            int r = i / HW;
            int c = i - r * HW;
            sm_x[r * ROWPAD + c] = xb[i];
        }
        __syncthreads();

        if (t < rows_here) {
            const float4* m4  = (const float4*)sm_m;
            const float4* xr4 = (const float4*)(sm_x + t * ROWPAD);
            float4 xv[13];
            #pragma unroll
            for (int i = 0; i < 13; ++i) xv[i] = xr4[i];

            float a0 = 0.f, a1 = 0.f, a2 = 0.f, a3 = 0.f;
            float a4 = 0.f, a5 = 0.f, a6 = 0.f, a7 = 0.f;
            #pragma unroll
            for (int kk = 0; kk < 13; ++kk) {
                float vv[4] = {xv[kk].x, xv[kk].y, xv[kk].z, xv[kk].w};
                #pragma unroll
                for (int e = 0; e < 4; ++e) {
                    int k = kk * 4 + e;
                    if (k < HW) {
                        float v = vv[e];
                        float4 m0 = m4[2 * k];
                        float4 m1 = m4[2 * k + 1];
                        a0 += v * m0.x; a1 += v * m0.y; a2 += v * m0.z; a3 += v * m0.w;
                        a4 += v * m1.x; a5 += v * m1.y; a6 += v * m1.z; a7 += v * m1.w;
                    }
                }
            }
            const long long row = row0 + t;
            float4* o = (float4*)(out + row * 8);
            o[0] = make_float4(a0, a1, a2, a3);
            o[1] = make_float4(a4, a5, a6, a7);
        }
    } else {
        // ------------- sal_feat part: one block per batch b -------------
        const int b = blk - nfb;
        const int M = 8 * N;
        const float* sb = s + (long long)b * SROW;
        float* sm_s = sm;

        for (int i = t; i < SROW; i += TPB) sm_s[i] = sb[i];

        const bool stage_idx = (SROW + M) <= SMEM_FLOATS;
        int* sm_idx = (int*)(sm + SROW);
        if (stage_idx) {
            for (int i = t; i < M; i += TPB) sm_idx[i] = sal_idx[i];
        }
        __syncthreads();

        float* ob = out + feat_elems + (long long)b * M;
        if (stage_idx) {
            for (int q = t; q < M; q += TPB) {
                int n = q >> 3;
                int p = q & 7;
                ob[q] = sm_s[sm_idx[p * N + n]];
            }
        } else {
            for (int q = t; q < M; q += TPB) {
                int n = q >> 3;
                int p = q & 7;
                ob[q] = sm_s[sal_idx[p * N + n]];
            }
        }
    }
}

extern "C" void kernel_launch(void* const* d_in, const int* in_sizes, int n_in,
                              void* d_out, int out_size) {
    const float* x       = (const float*)d_in[0];
    const float* s       = (const float*)d_in[1];
    const float* fm      = (const float*)d_in[2];
    const int*   sal_idx = (const int*)d_in[3];
    float*       out     = (float*)d_out;

    const int rows = in_sizes[0] / HW;    // B*C
    const int B    = in_sizes[1] / SROW;  // batch
    const int N    = in_sizes[3] / 8;     // saliency points per direction
    const int nfb  = (rows + TPB - 1) / TPB;
    const long long feat_elems = (long long)rows * 8;

    prep_mask_kernel<<<1, 128>>>(fm);
    fused_kernel<<<nfb + B, TPB>>>(x, s, sal_idx, out, rows, nfb, N, feat_elems);
}

// round 2
// speedup vs baseline: 1.2382x; 1.2382x over previous
#include <cuda_runtime.h>

// MultiDirectionPattern: masked 8-direction pooling + saliency gather.
//
// Inputs (metadata order):
//   d_in[0]: x         float32 (B, C, 7, 7)
//   d_in[1]: s         float32 (B, 1, 56, 56)
//   d_in[2]: feat_mask float32 (8, 7, 7)
//   d_in[3]: sal_idx   int32   (8, N)
// Output (float32): feat (B,C,2,4) then sal_feat (B,N,2,4)
//
// Fast path exploits the deterministic sector structure of the 7x7 8-direction
// mask (each direction = 10 cells incl. center, weight 1/10). A prep kernel
// VERIFIES the input mask matches; otherwise a generic dense fallback is used.

static constexpr int HW   = 49;    // 7*7
static constexpr int TPB  = 128;
static constexpr int SROW = 3136;  // 56*56
static constexpr int SMEM_FLOATS = 6448;  // 25792 B -> 9 CTAs/SM

// Expected nonzero cells per direction (incl. center 24), 10 each.
__constant__ unsigned char c_idx[80] = {
    24,25,26,27,32,33,34,40,41,48,
    24,31,32,38,39,40,45,46,47,48,
    24,30,31,36,37,38,42,43,44,45,
    21,22,23,24,28,29,30,35,36,42,
     0, 7, 8,14,15,16,21,22,23,24,
     0, 1, 2, 3, 8, 9,10,16,17,24,
     3, 4, 5, 6,10,11,12,17,18,24,
     6,12,13,18,19,20,24,25,26,27
};

__device__ int   g_fallback;
__device__ float g_mask_t[8 * HW];   // fallback: mask[p][k]/count[p], transposed [k][p]

__global__ void prep_kernel(const float* __restrict__ fm) {
    __shared__ float invc[8];
    __shared__ unsigned long long mb[8];
    __shared__ int bad;
    int t = threadIdx.x;
    if (t == 0) bad = 0;
    if (t < 8) {
        unsigned long long m = 0;
        #pragma unroll
        for (int j = 0; j < 10; ++j) m |= 1ULL << c_idx[t * 10 + j];
        mb[t] = m;
        int c = 0;
        for (int k = 0; k < HW; ++k) c += (fm[t * HW + k] != 0.0f) ? 1 : 0;
        invc[t] = 1.0f / (float)c;
    }
    __syncthreads();
    for (int i = t; i < 8 * HW; i += blockDim.x) {
        int p = i / HW, k = i - p * HW;
        float v = fm[p * HW + k];
        float e = ((mb[p] >> k) & 1ULL) ? 1.0f : 0.0f;
        if (v != e) atomicOr(&bad, 1);
        g_mask_t[k * 8 + p] = v * invc[p];
    }
    __syncthreads();
    if (t == 0) g_fallback = bad;
}

__global__ __launch_bounds__(TPB, 9) void fused_kernel(
    const float* __restrict__ x,
    const float* __restrict__ s,
    const int*   __restrict__ sal_idx,
    float*       __restrict__ out,
    int rows,             // B*C
    int nfb,              // feat blocks
    int N,                // saliency points per direction
    long long feat_elems  // rows*8
) {
    __shared__ __align__(16) float sm[SMEM_FLOATS];
    const int blk = blockIdx.x;
    const int t   = threadIdx.x;

    if (blk < nfb) {
        // ---------------- feat: 128 rows x 49 floats ----------------
        const long long row0 = (long long)blk * TPB;
        int rows_here = rows - (int)row0;
        if (rows_here > TPB) rows_here = TPB;
        const float* xb = x + row0 * HW;
        const int total = rows_here * HW;
        const int n4 = total >> 2;
        const float4* xb4 = (const float4*)xb;   // 16B aligned: row0*49*4 % 16 == 0
        float4* sm4 = (float4*)sm;
        for (int i = t; i < n4; i += TPB) sm4[i] = xb4[i];
        for (int i = 4 * n4 + t; i < total; i += TPB) sm[i] = xb[i];
        __syncthreads();

        if (t < rows_here) {
            const float* xr = sm + t * HW;   // stride 49: odd -> conflict-free LDS
            float o[8];
            if (!g_fallback) {
                const float x24 = xr[24];
                // Ray triples (shared by adjacent sectors)
                float R0 = xr[25] + xr[26] + xr[27];
                float R1 = xr[32] + xr[40] + xr[48];
                float R2 = xr[31] + xr[38] + xr[45];
                float R3 = xr[30] + xr[36] + xr[42];
                float R4 = xr[21] + xr[22] + xr[23];
                float R5 = xr[ 0] + xr[ 8] + xr[16];
                float R6 = xr[ 3] + xr[10] + xr[17];
                float R7 = xr[ 6] + xr[12] + xr[18];
                // Interior triples
                float I0 = xr[33] + xr[34] + xr[41];
                float I1 = xr[39] + xr[46] + xr[47];
                float I2 = xr[37] + xr[43] + xr[44];
                float I3 = xr[28] + xr[29] + xr[35];
                float I4 = xr[ 7] + xr[14] + xr[15];
                float I5 = xr[ 1] + xr[ 2] + xr[ 9];
                float I6 = xr[ 4] + xr[ 5] + xr[11];
                float I7 = xr[13] + xr[19] + xr[20];
                const float w = 0.1f;
                o[0] = (R0 + I0 + R1 + x24) * w;
                o[1] = (R1 + I1 + R2 + x24) * w;
                o[2] = (R2 + I2 + R3 + x24) * w;
                o[3] = (R3 + I3 + R4 + x24) * w;
                o[4] = (R4 + I4 + R5 + x24) * w;
                o[5] = (R5 + I5 + R6 + x24) * w;
                o[6] = (R6 + I6 + R7 + x24) * w;
                o[7] = (R7 + I7 + R0 + x24) * w;
            } else {
                // generic dense fallback (correct for any mask)
                float a[8] = {0, 0, 0, 0, 0, 0, 0, 0};
                for (int k = 0; k < HW; ++k) {
                    float v = xr[k];
                    #pragma unroll
                    for (int p = 0; p < 8; ++p) a[p] += v * g_mask_t[k * 8 + p];
                }
                #pragma unroll
                for (int p = 0; p < 8; ++p) o[p] = a[p];
            }
            float4* op = (float4*)(out + (row0 + t) * 8);
            op[0] = make_float4(o[0], o[1], o[2], o[3]);
            op[1] = make_float4(o[4], o[5], o[6], o[7]);
        }
    } else {
        // ---------------- sal_feat: one block per batch ----------------
        const int b = blk - nfb;
        const int M = 8 * N;
        const float* sb = s + (long long)b * SROW;
        for (int i = t; i < SROW; i += TPB) sm[i] = sb[i];

        const bool stage_idx = (SROW + M) <= SMEM_FLOATS;
        int* sm_idx = (int*)(sm + SROW);
        if (stage_idx) {
            for (int i = t; i < M; i += TPB) sm_idx[i] = sal_idx[i];
        }
        __syncthreads();

        float* ob = out + feat_elems + (long long)b * M;
        if (stage_idx) {
            for (int q = t; q < M; q += TPB) {
                int n = q >> 3;
                int p = q & 7;
                ob[q] = sm[sm_idx[p * N + n]];
            }
        } else {
            for (int q = t; q < M; q += TPB) {
                int n = q >> 3;
                int p = q & 7;
                ob[q] = sm[sal_idx[p * N + n]];
            }
        }
    }
}

extern "C" void kernel_launch(void* const* d_in, const int* in_sizes, int n_in,
                              void* d_out, int out_size) {
    const float* x       = (const float*)d_in[0];
    const float* s       = (const float*)d_in[1];
    const float* fm      = (const float*)d_in[2];
    const int*   sal_idx = (const int*)d_in[3];
    float*       out     = (float*)d_out;

    const int rows = in_sizes[0] / HW;    // B*C
    const int B    = in_sizes[1] / SROW;  // batch
    const int N    = in_sizes[3] / 8;     // points per direction
    const int nfb  = (rows + TPB - 1) / TPB;
    const long long feat_elems = (long long)rows * 8;

    prep_kernel<<<1, 128>>>(fm);
    fused_kernel<<<nfb + B, TPB>>>(x, s, sal_idx, out, rows, nfb, N, feat_elems);
}

// round 3
// speedup vs baseline: 1.7260x; 1.3939x over previous
#include <cuda_runtime.h>
#include <cstdint>

// MultiDirectionPattern: masked 8-direction pooling + saliency gather.
//
// Inputs (metadata order):
//   d_in[0]: x         float32 (B, C, 7, 7)
//   d_in[1]: s         float32 (B, 1, 56, 56)
//   d_in[2]: feat_mask float32 (8, 7, 7)
//   d_in[3]: sal_idx   int32   (8, N)
// Output (float32): feat (B,C,2,4) then sal_feat (B,N,2,4)
//
// Single kernel. Feat blocks stage x tiles with cp.async (high MLP), verify the
// 8-direction sector mask in-flight, and use a closed-form 10-cell/direction
// fast path (generic dense fallback if mask differs).

static constexpr int HW   = 49;    // 7*7
static constexpr int TPB  = 128;
static constexpr int SROW = 3136;  // 56*56
static constexpr int XF   = TPB * HW;       // 6272 floats per x tile
static constexpr int SM_FLOATS = XF + 392;  // 6664 floats = 26656 B -> 8 CTAs/SM

// Expected nonzero cells per direction (incl. center 24), 10 each.
__constant__ unsigned char c_idx[80] = {
    24,25,26,27,32,33,34,40,41,48,
    24,31,32,38,39,40,45,46,47,48,
    24,30,31,36,37,38,42,43,44,45,
    21,22,23,24,28,29,30,35,36,42,
     0, 7, 8,14,15,16,21,22,23,24,
     0, 1, 2, 3, 8, 9,10,16,17,24,
     3, 4, 5, 6,10,11,12,17,18,24,
     6,12,13,18,19,20,24,25,26,27
};

__device__ __forceinline__ void cp16(uint32_t dst_smem, const void* src) {
    asm volatile("cp.async.cg.shared.global [%0], [%1], 16;\n"
                 :: "r"(dst_smem), "l"(src));
}
__device__ __forceinline__ void cp_commit() {
    asm volatile("cp.async.commit_group;\n" ::: "memory");
}
__device__ __forceinline__ void cp_wait_all() {
    asm volatile("cp.async.wait_group 0;\n" ::: "memory");
}

__global__ __launch_bounds__(TPB, 8) void fused_kernel(
    const float* __restrict__ x,
    const float* __restrict__ s,
    const float* __restrict__ fm,
    const int*   __restrict__ sal_idx,
    float*       __restrict__ out,
    int rows,             // B*C
    int B,                // batch (sal blocks come first)
    int N,                // saliency points per direction
    long long feat_elems  // rows*8
) {
    __shared__ __align__(16) float sm[SM_FLOATS];
    const int blk = blockIdx.x;
    const int t   = threadIdx.x;
    const uint32_t sbase = (uint32_t)__cvta_generic_to_shared(sm);

    if (blk >= B) {
        // ---------------- feat: 128 rows x 49 floats ----------------
        const long long row0 = (long long)(blk - B) * TPB;
        int rows_here = rows - (int)row0;
        if (rows_here > TPB) rows_here = TPB;
        const float* xb = x + row0 * HW;     // 16B aligned (128*49*4 % 16 == 0)
        const int total = rows_here * HW;
        const int n4 = total >> 2;
        const float4* xb4 = (const float4*)xb;

        // async stage of x tile: ~12 outstanding 16B copies per thread
        for (int i = t; i < n4; i += TPB) cp16(sbase + i * 16, xb4 + i);
        cp_commit();
        for (int i = 4 * n4 + t; i < total; i += TPB) sm[i] = xb[i]; // tail (normally empty)

        // overlap: load + verify the mask while cp.async is in flight
        __shared__ unsigned long long mb[8];
        __shared__ int bad;
        __shared__ float invc[8];
        float* sm_fm = sm + XF;
        if (t == 0) bad = 0;
        if (t < 8) {
            unsigned long long m = 0;
            #pragma unroll
            for (int j = 0; j < 10; ++j) m |= 1ULL << c_idx[t * 10 + j];
            mb[t] = m;
        }
        for (int i = t; i < 392; i += TPB) sm_fm[i] = fm[i];
        __syncthreads();  // mb + sm_fm visible (does not wait on cp.async)

        int mybad = 0;
        #pragma unroll
        for (int j = 0; j < 4; ++j) {
            int i = t + j * TPB;
            if (i < 392) {
                int p = i / HW, k = i - p * HW;
                float e = ((mb[p] >> k) & 1ULL) ? 1.0f : 0.0f;
                if (sm_fm[i] != e) mybad = 1;
            }
        }
        if (mybad) atomicOr(&bad, 1);

        cp_wait_all();
        __syncthreads();   // x tile ready; bad final

        const bool fb = (bad != 0);
        if (fb) {
            // build scaled transposed weights, overlaying sm_fm in place
            if (t < 8) {
                int c = 0;
                for (int k = 0; k < HW; ++k) c += (sm_fm[t * HW + k] != 0.0f) ? 1 : 0;
                invc[t] = 1.0f / (float)c;
            }
            __syncthreads();
            float v[4]; int ii[4];
            #pragma unroll
            for (int j = 0; j < 4; ++j) {
                int i = t + j * TPB;
                ii[j] = -1;
                if (i < 392) {
                    int p = i / HW, k = i - p * HW;
                    v[j] = sm_fm[i] * invc[p];
                    ii[j] = k * 8 + p;
                }
            }
            __syncthreads();
            #pragma unroll
            for (int j = 0; j < 4; ++j) if (ii[j] >= 0) sm_fm[ii[j]] = v[j];
            __syncthreads();
        }

        if (t < rows_here) {
            const float* xr = sm + t * HW;   // stride 49 (odd): conflict-free LDS
            float o[8];
            if (!fb) {
                const float x24 = xr[24];
                float R0 = xr[25] + xr[26] + xr[27];
                float R1 = xr[32] + xr[40] + xr[48];
                float R2 = xr[31] + xr[38] + xr[45];
                float R3 = xr[30] + xr[36] + xr[42];
                float R4 = xr[21] + xr[22] + xr[23];
                float R5 = xr[ 0] + xr[ 8] + xr[16];
                float R6 = xr[ 3] + xr[10] + xr[17];
                float R7 = xr[ 6] + xr[12] + xr[18];
                float I0 = xr[33] + xr[34] + xr[41];
                float I1 = xr[39] + xr[46] + xr[47];
                float I2 = xr[37] + xr[43] + xr[44];
                float I3 = xr[28] + xr[29] + xr[35];
                float I4 = xr[ 7] + xr[14] + xr[15];
                float I5 = xr[ 1] + xr[ 2] + xr[ 9];
                float I6 = xr[ 4] + xr[ 5] + xr[11];
                float I7 = xr[13] + xr[19] + xr[20];
                const float w = 0.1f;
                o[0] = (R0 + I0 + R1 + x24) * w;
                o[1] = (R1 + I1 + R2 + x24) * w;
                o[2] = (R2 + I2 + R3 + x24) * w;
                o[3] = (R3 + I3 + R4 + x24) * w;
                o[4] = (R4 + I4 + R5 + x24) * w;
                o[5] = (R5 + I5 + R6 + x24) * w;
                o[6] = (R6 + I6 + R7 + x24) * w;
                o[7] = (R7 + I7 + R0 + x24) * w;
            } else {
                float a[8] = {0, 0, 0, 0, 0, 0, 0, 0};
                for (int k = 0; k < HW; ++k) {
                    float vv = xr[k];
                    const float4* w4 = (const float4*)(sm_fm + k * 8);
                    float4 m0 = w4[0], m1 = w4[1];
                    a[0] += vv * m0.x; a[1] += vv * m0.y; a[2] += vv * m0.z; a[3] += vv * m0.w;
                    a[4] += vv * m1.x; a[5] += vv * m1.y; a[6] += vv * m1.z; a[7] += vv * m1.w;
                }
                #pragma unroll
                for (int p = 0; p < 8; ++p) o[p] = a[p];
            }
            float4* op = (float4*)(out + (row0 + t) * 8);
            op[0] = make_float4(o[0], o[1], o[2], o[3]);
            op[1] = make_float4(o[4], o[5], o[6], o[7]);
        }
    } else {
        // ---------------- sal_feat: one block per batch ----------------
        const int b = blk;
        const int M = 8 * N;
        const float* sb = s + (long long)b * SROW;  // 12544B/row: 16B aligned
        const float4* sb4 = (const float4*)sb;
        for (int i = t; i < SROW / 4; i += TPB) cp16(sbase + i * 16, sb4 + i);

        const bool stage_idx = (SROW + M) <= SM_FLOATS;  // M % 4 == 0 always
        if (stage_idx) {
            const int4* si4 = (const int4*)sal_idx;
            for (int i = t; i < (M >> 2); i += TPB)
                cp16(sbase + SROW * 4 + i * 16, si4 + i);
        }
        cp_commit();
        cp_wait_all();
        __syncthreads();

        float* ob = out + feat_elems + (long long)b * M;
        int* sm_idx = (int*)(sm + SROW);
        if (stage_idx) {
            for (int q = t; q < M; q += TPB) {
                int n = q >> 3;
                int p = q & 7;
                ob[q] = sm[sm_idx[p * N + n]];
            }
        } else {
            for (int q = t; q < M; q += TPB) {
                int n = q >> 3;
                int p = q & 7;
                ob[q] = sm[sal_idx[p * N + n]];
            }
        }
    }
}

extern "C" void kernel_launch(void* const* d_in, const int* in_sizes, int n_in,
                              void* d_out, int out_size) {
    const float* x       = (const float*)d_in[0];
    const float* s       = (const float*)d_in[1];
    const float* fm      = (const float*)d_in[2];
    const int*   sal_idx = (const int*)d_in[3];
    float*       out     = (float*)d_out;

    const int rows = in_sizes[0] / HW;    // B*C
    const int B    = in_sizes[1] / SROW;  // batch
    const int N    = in_sizes[3] / 8;     // points per direction
    const int nfb  = (rows + TPB - 1) / TPB;
    const long long feat_elems = (long long)rows * 8;

    fused_kernel<<<B + nfb, TPB>>>(x, s, fm, sal_idx, out, rows, B, N, feat_elems);
}